// round 10
// baseline (speedup 1.0000x reference)
#include <cuda_runtime.h>
#include <stdint.h>

// Fixed problem shapes
#define NB 32
#define NS 32
#define NW 30
#define NE 300
#define NEV 75                   // float4 per embedding row (300 floats)
#define NSENT (NB * NS)          // 1024
#define EMB_ELEMS (NSENT * NW * NE)          // 9,216,000
#define OFF_SHARE  EMB_ELEMS
#define OFF_MASK   (2 * EMB_ELEMS)           // 18,432,000
#define OFF_WMASK  (OFF_MASK + NSENT * NW)
#define OFF_SMASK  (OFF_WMASK + NSENT * NW)

#define HALF_ROWS 15
#define HALF_VEC  (HALF_ROWS * NEV)          // 1125 float4 per half-sentence
#define BLOCK     256
#define NITER     5

// Gather load with L2 evict-last policy (keep W_emb resident vs streaming output)
__device__ __forceinline__ float4 ldg_el(const float4* p, uint64_t pol) {
    float4 v;
    asm volatile("ld.global.nc.L2::cache_hint.v4.f32 {%0,%1,%2,%3}, [%4], %5;"
                 : "=f"(v.x), "=f"(v.y), "=f"(v.z), "=f"(v.w)
                 : "l"(p), "l"(pol));
    return v;
}

__global__ __launch_bounds__(BLOCK, 8) void embed_fused_kernel(
    const int* __restrict__ input_var,        // [1024*30] int32 tokens
    const float* __restrict__ W_emb,          // [50000*300]
    float* __restrict__ out)
{
    const int sent = blockIdx.x >> 1;   // 0..1023
    const int half = blockIdx.x & 1;    // 0: rows 0-14, 1: rows 15-29
    const int tid  = threadIdx.x;

    uint64_t pol;
    asm("createpolicy.fractional.L2::evict_last.b64 %0, 1.0;" : "=l"(pol));

    __shared__ int s_tok[NW];
    __shared__ unsigned s_kmask;        // bit w set => token w kept (before first zero)

    // Warp 0: load tokens + compute all masks with one ballot
    if (tid < 32) {
        const int t = (tid < NW) ? input_var[sent * NW + tid] : 1;
        if (tid < NW) s_tok[tid] = t;
        const unsigned nz = __ballot_sync(0xFFFFFFFFu, t != 0);
        const unsigned firstzero = ~nz;                 // lowest set bit = first zero
        const unsigned keepmask  = (firstzero - 1u) & ~firstzero & 0x3FFFFFFFu;
        if (tid == 0) s_kmask = keepmask;
        if (half == 0 && tid < NW) {
            out[OFF_MASK  + sent * NW + tid] = (keepmask >> tid & 1u) ? 1.0f : 0.0f;
            out[OFF_WMASK + sent * NW + tid] = (t != 0) ? 1.0f : 0.0f;
        }
        if (half == 0 && tid == 0) {
            out[OFF_SMASK + sent] = ((nz & 0x3FFFFFFFu) != 0u) ? 1.0f : 0.0f;
        }
    }
    __syncthreads();

    const unsigned kmask = s_kmask;
    const float4* __restrict__ emb4 = (const float4*)W_emb;
    float4* __restrict__ out_e = (float4*)out
        + (size_t)sent * (NW * NEV) + half * HALF_VEC;
    float4* __restrict__ out_s = (float4*)(out + OFF_SHARE)
        + (size_t)sent * (NW * NEV) + half * HALF_VEC;
    const int rbase = half * HALF_ROWS;

    // Phase 1: batched gathers. i=0..3 provably in-bounds (tid+768 <= 1023 < 1125)
    // -> 4 unconditional LDG.128 front-batched; only i=4 predicated.
    float4 vals[NITER];
    #pragma unroll
    for (int i = 0; i < 4; i++) {
        const int v = tid + i * BLOCK;
        const int w = v / NEV;
        const int j = v - w * NEV;
        vals[i] = ldg_el(&emb4[(size_t)s_tok[rbase + w] * NEV + j], pol);
    }
    const int v4 = tid + 4 * BLOCK;
    if (v4 < HALF_VEC) {
        const int w = v4 / NEV;
        const int j = v4 - w * NEV;
        vals[4] = ldg_el(&emb4[(size_t)s_tok[rbase + w] * NEV + j], pol);
    }

    // Phase 2: streaming stores; rare truncated token -> row 0 (predicated reload)
    #pragma unroll
    for (int i = 0; i < NITER; i++) {
        const int v = tid + i * BLOCK;
        if (i < 4 || v < HALF_VEC) {
            const int w = v / NEV;
            const int j = v - w * NEV;
            __stcs(&out_e[v], vals[i]);
            float4 x = vals[i];
            if (!(kmask >> (rbase + w) & 1u)) x = ldg_el(&emb4[j], pol);  // row 0
            __stcs(&out_s[v], x);
        }
    }
}

extern "C" void kernel_launch(void* const* d_in, const int* in_sizes, int n_in,
                              void* d_out, int out_size) {
    const int*   input_var = (const int*)d_in[0];
    const float* W_emb     = (const float*)d_in[1];
    float*       out       = (float*)d_out;

    embed_fused_kernel<<<2 * NSENT, BLOCK>>>(input_var, W_emb, out);
}